// round 11
// baseline (speedup 1.0000x reference)
#include <cuda_runtime.h>
#include <math.h>

#define Nn 8192
#define Dd 4
#define Ff 256
#define Hh 512
#define Aa 64
#define Ee (Nn*Dd)
#define G4 2048
#define NCTA2 64  /* CTAs total; each handles BOTH directions */
#define ZPAD 16   /* floats between z slots: 64B -> spreads atomics across LTS */
#define CPAD 32   /* ints per counter slot: own 128B line */

// ---------------- device scratch (no cudaMalloc allowed) ----------------
__device__ float g_preF[(size_t)Ee*G4];           // edges @ Wih_f^T + b_f
__device__ float g_preB[(size_t)Ee*G4];           // edges @ Wih_b^T + b_b
__device__ float g_arcA[(size_t)Ee*Hh];           // fwd arc_h (== ef, edge layout)
__device__ float g_arcB[(size_t)Ee*Hh];           // bwd arc_h at [node][slot]
__device__ float g_z  [2][(size_t)Nn*Dd*Aa*ZPAD]; // padded attention accumulators
__device__ float g_hid[(size_t)Ee*Hh];            // decoder hidden
__device__ int   g_cz[2][(size_t)Nn*CPAD];

// ---------------- helpers ----------------
__device__ __forceinline__ int ld_acq(const int* p){
    int v; asm volatile("ld.acquire.gpu.b32 %0,[%1];":"=r"(v):"l"(p):"memory"); return v;
}
__device__ __forceinline__ void red_rel(int* p){
    asm volatile("red.release.gpu.global.add.s32 [%0], 1;"::"l"(p):"memory");
}
__device__ __forceinline__ float fsig(float x){ return 1.f/(1.f+__expf(-x)); }
__device__ __forceinline__ float ftanh(float x){
    float e = __expf(-2.f*fabsf(x));
    float t = (1.f-e)/(1.f+e);
    return copysignf(t, x);
}
__device__ __forceinline__ void ffma2(unsigned long long& acc,
                                      unsigned long long a, unsigned long long b){
    asm("fma.rn.f32x2 %0, %1, %2, %0;" : "+l"(acc) : "l"(a), "l"(b));
}

// ---------------- init: counters + z-seed (ba + x[:3] @ Wa[:,512:515]^T) ---
__global__ void init_kernel(const float* __restrict__ edges,
                            const float* __restrict__ Wa,
                            const float* __restrict__ ba)
{
    int idx = blockIdx.x*256 + threadIdx.x;        // 0 .. 2^22-1
    if (idx < Nn*CPAD){
        g_cz[0][idx]=0; g_cz[1][idx]=0;
    }
    int dir = idx >> 21;
    int rem = idx & ((1<<21)-1);
    int i = rem >> 8;
    int d = (rem >> 6) & 3;
    int a = rem & 63;
    float z = ba[a];
    size_t e = 0; bool ok = true;
    if (dir == 0) e = (size_t)i*4 + d;
    else { int cn = i+1+d; if (cn < Nn) e = (size_t)cn*4 + d; else ok = false; }
    if (ok){
        const float* x  = edges + e*Ff;
        const float* wr = Wa + (size_t)a*(Hh+3) + Hh;
        z += x[0]*wr[0] + x[1]*wr[1] + x[2]*wr[2];
    }
    g_z[dir][((size_t)i*256 + d*64 + a)*ZPAD] = z;
}

// ------------- SGEMM: C[M,Nc] = A[M,K] @ B[Nc,K]^T + bias (opt relu) -------
// mode 0: plain A.  mode 1: A rows are feat[e] = [ef[e] | eb[e]] gathered.
__global__ void __launch_bounds__(256) gemm_kernel(
    const float* __restrict__ A, const float* __restrict__ B,
    const float* __restrict__ bias, float* __restrict__ C,
    int M, int Nc, int K, int mode)
{
    __shared__ float sA[16][132];
    __shared__ float sB[16][132];
    int tid = threadIdx.x;
    int n0 = blockIdx.x * 128;
    int m0 = blockIdx.y * 128;
    int tx = tid & 15, ty = tid >> 4;
    float acc[8][8];
    #pragma unroll
    for (int ii=0; ii<8; ii++)
        #pragma unroll
        for (int jj=0; jj<8; jj++) acc[ii][jj] = 0.f;

    for (int k0 = 0; k0 < K; k0 += 16){
        #pragma unroll
        for (int u = 0; u < 2; u++){
            int v = tid + u*256;
            int row = v >> 2, kq = v & 3;
            float4 va;
            if (mode == 0){
                va = *(const float4*)(A + (size_t)(m0+row)*K + k0 + kq*4);
            } else {
                int e = m0 + row;
                int kk = k0 + kq*4;
                if (kk < Hh){
                    va = *(const float4*)(g_arcA + (size_t)e*Hh + kk);
                } else {
                    int d = e & 3, j = e >> 2;
                    if (j >= 1+d)
                        va = *(const float4*)(g_arcB + (size_t)(e - 4*(1+d))*Hh + (kk - Hh));
                    else
                        va = make_float4(0.f,0.f,0.f,0.f);
                }
            }
            sA[kq*4+0][row]=va.x; sA[kq*4+1][row]=va.y;
            sA[kq*4+2][row]=va.z; sA[kq*4+3][row]=va.w;
            float4 vb = *(const float4*)(B + (size_t)(n0+row)*K + k0 + kq*4);
            sB[kq*4+0][row]=vb.x; sB[kq*4+1][row]=vb.y;
            sB[kq*4+2][row]=vb.z; sB[kq*4+3][row]=vb.w;
        }
        __syncthreads();
        #pragma unroll
        for (int k=0; k<16; k++){
            float4 a0 = *(const float4*)&sA[k][ty*8];
            float4 a1 = *(const float4*)&sA[k][ty*8+4];
            float4 b0 = *(const float4*)&sB[k][tx*8];
            float4 b1 = *(const float4*)&sB[k][tx*8+4];
            float av[8] = {a0.x,a0.y,a0.z,a0.w,a1.x,a1.y,a1.z,a1.w};
            float bv[8] = {b0.x,b0.y,b0.z,b0.w,b1.x,b1.y,b1.z,b1.w};
            #pragma unroll
            for (int ii=0; ii<8; ii++)
                #pragma unroll
                for (int jj=0; jj<8; jj++)
                    acc[ii][jj] = fmaf(av[ii], bv[jj], acc[ii][jj]);
        }
        __syncthreads();
    }
    #pragma unroll
    for (int ii=0; ii<8; ii++){
        int m = m0 + ty*8 + ii;
        #pragma unroll
        for (int jj=0; jj<8; jj++){
            int n = n0 + tx*8 + jj;
            float v = acc[ii][jj] + bias[n];
            if (mode == 1) v = fmaxf(v, 0.f);
            C[(size_t)m*Nc + n] = v;
        }
    }
}

// ---------------- persistent MERGED bidirectional recurrence ---------------
// 64 CTAs x 512 threads. CTA ct owns h-dims [ct*8, ct*8+8) for BOTH dirs.
// Each direction's barrier latency is covered by the sibling direction's
// phases + prefetches. One flag per node per direction, 64 arrivals.
__global__ void __launch_bounds__(512, 1) recur_kernel(
    const float* __restrict__ Whh_f, const float* __restrict__ Whh_b,
    const float* __restrict__ Wa, const float* __restrict__ Wao,
    const float* __restrict__ bao)
{
    const int ct  = blockIdx.x;        // 0..63
    const int tid = threadIdx.x;
    const int w = tid >> 5, l = tid & 31;

    __shared__ float sWa[8][64];
    __shared__ float sWao[64];
    __shared__ float sbao;
    __shared__ float h_s[2][4][8];
    __shared__ float carc_s[2][4][8];
    __shared__ float logit_s[2][4];
    __shared__ __align__(16) float hn_s[2][512];
    __shared__ float u_ring[2][4][32];   // [dir][node&3][g*8+q]
    __shared__ float c_ring[2][4][8];    // [dir][node&3][q]

    for (int x = tid; x < 8*64; x += 512){
        int q = x >> 6, a = x & 63;
        sWa[q][a] = Wa[(size_t)a*(Hh+3) + ct*8 + q];
    }
    if (tid < 64) sWao[tid] = Wao[tid];
    if (tid == 0) sbao = bao[0];

    // matvec mapping: thread -> local row r=tid>>4 (gate g=r>>3, dim q=r&7),
    // column-pairs (m*16+sub)*2, m=0..15, sub=tid&15 (conflict-free)
    const int r   = tid >> 4;
    const int sub = tid & 15;
    const int rowG = (r >> 3)*Hh + ct*8 + (r & 7);
    float2 wfF[16], wfB[16];
    #pragma unroll
    for (int m=0; m<16; m++){
        wfF[m] = *(const float2*)(Whh_f + (size_t)rowG*Hh + (m*16 + sub)*2);
        wfB[m] = *(const float2*)(Whh_b + (size_t)rowG*Hh + (m*16 + sub)*2);
    }
    __syncthreads();

    // cell mapping (warps 0=fwd, 1=bwd): lanes l -> arc dA, dim qA
    const int dA = l >> 3, qA = l & 7;
    const int jj = ct*8 + qA;

    float pg[4] = {0.f,0.f,0.f,0.f};   // t=0: all arcs invalid -> zeros

    for (int t = 0; t < Nn; t++){
        const int in = t, jn = Nn-1-t;

        // ---- A: cells, both dirs in parallel (warps 0,1) ---------------
        if (w < 2){
            const int node = w ? jn : in;
            float ha = 0.f, ca = 0.f;
            if (t > dA){                          // unified validity
                int p  = w ? (node+1+dA) : (node-1-dA);
                int ps = p & 3;
                float gi = pg[0] + u_ring[w][ps][qA];
                float gf = pg[1] + u_ring[w][ps][8 + qA];
                float gg = pg[2] + u_ring[w][ps][16 + qA];
                float go = pg[3] + u_ring[w][ps][24 + qA];
                float cp = c_ring[w][ps][qA];
                ca = fsig(gf)*cp + fsig(gi)*ftanh(gg);
                ha = fsig(go)*ftanh(ca);
            }
            h_s[w][dA][qA] = ha; carc_s[w][dA][qA] = ca;
            float* arcp = w ? g_arcB : g_arcA;
            __stcg(arcp + ((size_t)node*4 + dA)*Hh + jj, ha);
        }
        __syncthreads();

        // ---- B: z partials, both dirs (512 threads, 256 targets each) --
        {
            int dirIdx = tid >> 8, loc = tid & 255;
            int d = loc >> 6, a = loc & 63;
            float v = 0.f;
            #pragma unroll
            for (int q=0; q<8; q++) v = fmaf(sWa[q][a], h_s[dirIdx][d][q], v);
            int node = dirIdx ? jn : in;
            atomicAdd(&g_z[dirIdx][((size_t)node*256 + loc)*ZPAD], v);
        }
        __syncthreads();

        // ---- C: release both flags ASAP --------------------------------
        if (tid == 64) red_rel(&g_cz[0][(size_t)in*CPAD]);
        if (tid == 96) red_rel(&g_cz[1][(size_t)jn*CPAD]);

        // ---- D: prefetch next step's pre (both dirs, warps 0,1) --------
        if (w < 2){
            pg[0]=pg[1]=pg[2]=pg[3]=0.f;
            if (t+1 < Nn && t+1 > dA){
                int nn = w ? (jn-1) : (in+1);
                size_t e = w ? ((size_t)(nn+1+dA)*4 + dA) : ((size_t)nn*4 + dA);
                const float* pr = (w ? g_preB : g_preF) + e*G4;
                pg[0]=__ldg(pr+jj); pg[1]=__ldg(pr+Hh+jj);
                pg[2]=__ldg(pr+2*Hh+jj); pg[3]=__ldg(pr+3*Hh+jj);
            }
        }

        // ---- E: poll both flags concurrently (warps 2,3) ---------------
        if (tid == 64){ while (ld_acq(&g_cz[0][(size_t)in*CPAD]) < NCTA2) {} }
        if (tid == 96){ while (ld_acq(&g_cz[1][(size_t)jn*CPAD]) < NCTA2) {} }
        __syncthreads();

        // ---- F: arc loads (independent) + logits (warps 0-7) -----------
        float avF[4], avB[4];
        #pragma unroll
        for (int d=0; d<4; d++){
            avF[d] = __ldcg(g_arcA + ((size_t)in*4 + d)*Hh + tid);
            avB[d] = __ldcg(g_arcB + ((size_t)jn*4 + d)*Hh + tid);
        }
        if (w < 8){
            int dirIdx = w >> 2, arcd = w & 3;
            int node = dirIdx ? jn : in;
            float z1 = __ldcg(&g_z[dirIdx][((size_t)node*256 + arcd*64 + l)*ZPAD]);
            float z2 = __ldcg(&g_z[dirIdx][((size_t)node*256 + arcd*64 + l + 32)*ZPAD]);
            float s = fmaxf(z1, 0.f)*sWao[l] + fmaxf(z2, 0.f)*sWao[l + 32];
            #pragma unroll
            for (int off=16; off; off >>= 1) s += __shfl_xor_sync(0xffffffffu, s, off);
            if (l == 0) logit_s[dirIdx][arcd] = ftanh(s + sbao);
        }
        __syncthreads();

        // ---- G: softmax both dirs (logits bounded: no max-shift needed),
        //         h_node slices, c_node rings ----------------------------
        float wgtF[4], wgtB[4];
        {
            float sF = 0.f, sB = 0.f;
            #pragma unroll
            for (int d=0; d<4; d++){
                float eF = (t > d) ? __expf(logit_s[0][d]) : 0.f;
                float eB = (t > d) ? __expf(logit_s[1][d]) : 0.f;
                wgtF[d] = eF; wgtB[d] = eB; sF += eF; sB += eB;
            }
            if (t > 0){
                float iF = 1.f/sF, iB = 1.f/sB;
                #pragma unroll
                for (int d=0; d<4; d++){ wgtF[d] *= iF; wgtB[d] *= iB; }
            }
        }
        {
            float hF = 0.f, hB = 0.f;
            #pragma unroll
            for (int d=0; d<4; d++){
                hF = fmaf(wgtF[d], avF[d], hF);
                hB = fmaf(wgtB[d], avB[d], hB);
            }
            hn_s[0][tid] = hF; hn_s[1][tid] = hB;
        }
        if (tid < 8){
            float c = 0.f;
            #pragma unroll
            for (int d=0; d<4; d++) c = fmaf(wgtF[d], carc_s[0][d][tid], c);
            c_ring[0][in & 3][tid] = c;
        } else if (tid < 16){
            int q = tid - 8;
            float c = 0.f;
            #pragma unroll
            for (int d=0; d<4; d++) c = fmaf(wgtB[d], carc_s[1][d][q], c);
            c_ring[1][jn & 3][q] = c;
        }
        __syncthreads();

        // ---- H: both matvecs (f32x2, conflict-free smem) ---------------
        {
            unsigned long long aF = 0ull, aB = 0ull;
            const unsigned long long* hF = (const unsigned long long*)hn_s[0];
            const unsigned long long* hB = (const unsigned long long*)hn_s[1];
            #pragma unroll
            for (int m=0; m<16; m++){
                ffma2(aF, *(const unsigned long long*)&wfF[m], hF[m*16 + sub]);
                ffma2(aB, *(const unsigned long long*)&wfB[m], hB[m*16 + sub]);
            }
            float sF = __uint_as_float((unsigned)aF) + __uint_as_float((unsigned)(aF >> 32));
            float sB = __uint_as_float((unsigned)aB) + __uint_as_float((unsigned)(aB >> 32));
            #pragma unroll
            for (int off=8; off; off >>= 1){
                sF += __shfl_xor_sync(0xffffffffu, sF, off);
                sB += __shfl_xor_sync(0xffffffffu, sB, off);
            }
            if (sub == 0){
                u_ring[0][in & 3][r] = sF;
                u_ring[1][jn & 3][r] = sB;
            }
        }
        __syncthreads();   // rings visible before next step's cells
    }
}

// ---------------- final: out[e] = hid[e] . Wdo + bdo --------------------
__global__ void final_kernel(const float* __restrict__ Wdo,
                             const float* __restrict__ bdo,
                             float* __restrict__ out)
{
    int gw = (blockIdx.x*blockDim.x + threadIdx.x) >> 5;
    int l = threadIdx.x & 31;
    if (gw >= Ee) return;
    const float* h = g_hid + (size_t)gw*Hh;
    float s = 0.f;
    #pragma unroll
    for (int q=0; q<16; q++) s = fmaf(h[l + q*32], Wdo[l + q*32], s);
    #pragma unroll
    for (int off=16; off; off >>= 1) s += __shfl_xor_sync(0xffffffffu, s, off);
    if (l == 0) out[gw] = s + bdo[0];
}

// ---------------- launch --------------------------------------------------
extern "C" void kernel_launch(void* const* d_in, const int* in_sizes, int n_in,
                              void* d_out, int out_size)
{
    const float* edges = (const float*)d_in[0];
    const float* Wih_f = (const float*)d_in[1];
    const float* Whh_f = (const float*)d_in[2];
    const float* b_f   = (const float*)d_in[3];
    const float* Wih_b = (const float*)d_in[4];
    const float* Whh_b = (const float*)d_in[5];
    const float* b_b   = (const float*)d_in[6];
    const float* Wa    = (const float*)d_in[7];
    const float* ba    = (const float*)d_in[8];
    const float* Wao   = (const float*)d_in[9];
    const float* bao   = (const float*)d_in[10];
    const float* Wd    = (const float*)d_in[11];
    const float* bd    = (const float*)d_in[12];
    const float* Wdo   = (const float*)d_in[13];
    const float* bdo   = (const float*)d_in[14];
    float* out = (float*)d_out;

    float *preF, *preB, *hid;
    cudaGetSymbolAddress((void**)&preF, g_preF);
    cudaGetSymbolAddress((void**)&preB, g_preB);
    cudaGetSymbolAddress((void**)&hid,  g_hid);

    // 1. counters + z seed
    init_kernel<<<16384, 256>>>(edges, Wa, ba);
    // 2. input-side GEMMs: pre = edges @ Wih^T + b
    gemm_kernel<<<dim3(G4/128, Ee/128), 256>>>(edges, Wih_f, b_f, preF, Ee, G4, Ff, 0);
    gemm_kernel<<<dim3(G4/128, Ee/128), 256>>>(edges, Wih_b, b_b, preB, Ee, G4, Ff, 0);
    // 3. merged bidirectional recurrence (64 CTAs, both dirs per CTA)
    recur_kernel<<<NCTA2, 512>>>(Whh_f, Whh_b, Wa, Wao, bao);
    // 4. decoder GEMM: hid = relu(feat @ Wd^T + bd), feat gathered from arcs
    gemm_kernel<<<dim3(Hh/128, Ee/128), 256>>>(nullptr, Wd, bd, hid, Ee, Hh, 2*Hh, 1);
    // 5. output projection
    final_kernel<<<(Ee*32)/256, 256>>>(Wdo, bdo, out);
}

// round 12
// speedup vs baseline: 1.2203x; 1.2203x over previous
#include <cuda_runtime.h>
#include <math.h>

#define Nn 8192
#define Dd 4
#define Ff 256
#define Hh 512
#define Aa 64
#define Ee (Nn*Dd)
#define G4 2048
#define NCTA 32   /* CTAs per direction */
#define ZG 16     /* floats per z group slot (4 data + 12 pad = 64B stride) */
#define CPAD 32   /* ints per counter slot: own 128B line */

// ---------------- device scratch (no cudaMalloc allowed) ----------------
__device__ float g_preF[(size_t)Ee*G4];           // edges @ Wih_f^T + b_f
__device__ float g_preB[(size_t)Ee*G4];           // edges @ Wih_b^T + b_b
__device__ float g_arcA[(size_t)Ee*Hh];           // fwd arc_h (== ef, edge layout)
__device__ float g_arcB[(size_t)Ee*Hh];           // bwd arc_h at [node][slot]
__device__ float g_z  [2][(size_t)Nn*64*ZG];      // z accumulators, v4 groups
__device__ float g_hid[(size_t)Ee*Hh];            // decoder hidden
__device__ int   g_cz[2][(size_t)Nn*CPAD];

// ---------------- helpers ----------------
__device__ __forceinline__ int ld_acq(const int* p){
    int v; asm volatile("ld.acquire.gpu.b32 %0,[%1];":"=r"(v):"l"(p):"memory"); return v;
}
__device__ __forceinline__ void red_rel(int* p){
    asm volatile("red.release.gpu.global.add.s32 [%0], 1;"::"l"(p):"memory");
}
__device__ __forceinline__ void red_v4(float* p, float a, float b, float c, float d){
    asm volatile("red.global.v4.f32.add [%0], {%1, %2, %3, %4};"
                 ::"l"(p),"f"(a),"f"(b),"f"(c),"f"(d):"memory");
}
__device__ __forceinline__ float fsig(float x){ return 1.f/(1.f+__expf(-x)); }
__device__ __forceinline__ float ftanh(float x){
    float e = __expf(-2.f*fabsf(x));
    float t = (1.f-e)/(1.f+e);
    return copysignf(t, x);
}
__device__ __forceinline__ void ffma2(unsigned long long& acc,
                                      unsigned long long a, unsigned long long b){
    asm("fma.rn.f32x2 %0, %1, %2, %0;" : "+l"(acc) : "l"(a), "l"(b));
}

// z slot address: node i, arc d, unit a  ->  i*1024 + (d*16 + a/4)*ZG + (a%4)
__device__ __forceinline__ size_t zaddr(int i, int d, int a){
    return (size_t)i*(64*ZG) + (size_t)(d*16 + (a>>2))*ZG + (a&3);
}

// ---------------- init: counters + z-seed (ba + x[:3] @ Wa[:,512:515]^T) ---
__global__ void init_kernel(const float* __restrict__ edges,
                            const float* __restrict__ Wa,
                            const float* __restrict__ ba)
{
    int idx = blockIdx.x*256 + threadIdx.x;        // 0 .. 2^22-1
    if (idx < Nn*CPAD){
        g_cz[0][idx]=0; g_cz[1][idx]=0;
    }
    int dir = idx >> 21;
    int rem = idx & ((1<<21)-1);
    int i = rem >> 8;
    int d = (rem >> 6) & 3;
    int a = rem & 63;
    float z = ba[a];
    size_t e = 0; bool ok = true;
    if (dir == 0) e = (size_t)i*4 + d;
    else { int cn = i+1+d; if (cn < Nn) e = (size_t)cn*4 + d; else ok = false; }
    if (ok){
        const float* x  = edges + e*Ff;
        const float* wr = Wa + (size_t)a*(Hh+3) + Hh;
        z += x[0]*wr[0] + x[1]*wr[1] + x[2]*wr[2];
    }
    g_z[dir][zaddr(i, d, a)] = z;
}

// ------------- SGEMM: C[M,Nc] = A[M,K] @ B[Nc,K]^T + bias (opt relu) -------
// mode 0: plain A.  mode 1: A rows are feat[e] = [ef[e] | eb[e]] gathered.
__global__ void __launch_bounds__(256) gemm_kernel(
    const float* __restrict__ A, const float* __restrict__ B,
    const float* __restrict__ bias, float* __restrict__ C,
    int M, int Nc, int K, int mode)
{
    __shared__ float sA[16][132];
    __shared__ float sB[16][132];
    int tid = threadIdx.x;
    int n0 = blockIdx.x * 128;
    int m0 = blockIdx.y * 128;
    int tx = tid & 15, ty = tid >> 4;
    float acc[8][8];
    #pragma unroll
    for (int ii=0; ii<8; ii++)
        #pragma unroll
        for (int jj=0; jj<8; jj++) acc[ii][jj] = 0.f;

    for (int k0 = 0; k0 < K; k0 += 16){
        #pragma unroll
        for (int u = 0; u < 2; u++){
            int v = tid + u*256;
            int row = v >> 2, kq = v & 3;
            float4 va;
            if (mode == 0){
                va = *(const float4*)(A + (size_t)(m0+row)*K + k0 + kq*4);
            } else {
                int e = m0 + row;
                int kk = k0 + kq*4;
                if (kk < Hh){
                    va = *(const float4*)(g_arcA + (size_t)e*Hh + kk);
                } else {
                    int d = e & 3, j = e >> 2;
                    if (j >= 1+d)
                        va = *(const float4*)(g_arcB + (size_t)(e - 4*(1+d))*Hh + (kk - Hh));
                    else
                        va = make_float4(0.f,0.f,0.f,0.f);
                }
            }
            sA[kq*4+0][row]=va.x; sA[kq*4+1][row]=va.y;
            sA[kq*4+2][row]=va.z; sA[kq*4+3][row]=va.w;
            float4 vb = *(const float4*)(B + (size_t)(n0+row)*K + k0 + kq*4);
            sB[kq*4+0][row]=vb.x; sB[kq*4+1][row]=vb.y;
            sB[kq*4+2][row]=vb.z; sB[kq*4+3][row]=vb.w;
        }
        __syncthreads();
        #pragma unroll
        for (int k=0; k<16; k++){
            float4 a0 = *(const float4*)&sA[k][ty*8];
            float4 a1 = *(const float4*)&sA[k][ty*8+4];
            float4 b0 = *(const float4*)&sB[k][tx*8];
            float4 b1 = *(const float4*)&sB[k][tx*8+4];
            float av[8] = {a0.x,a0.y,a0.z,a0.w,a1.x,a1.y,a1.z,a1.w};
            float bv[8] = {b0.x,b0.y,b0.z,b0.w,b1.x,b1.y,b1.z,b1.w};
            #pragma unroll
            for (int ii=0; ii<8; ii++)
                #pragma unroll
                for (int jj=0; jj<8; jj++)
                    acc[ii][jj] = fmaf(av[ii], bv[jj], acc[ii][jj]);
        }
        __syncthreads();
    }
    #pragma unroll
    for (int ii=0; ii<8; ii++){
        int m = m0 + ty*8 + ii;
        #pragma unroll
        for (int jj=0; jj<8; jj++){
            int n = n0 + tx*8 + jj;
            float v = acc[ii][jj] + bias[n];
            if (mode == 1) v = fmaxf(v, 0.f);
            C[(size_t)m*Nc + n] = v;
        }
    }
}

// ---------------- persistent bidirectional recurrence ----------------------
// 32 CTAs x 512 threads per direction. CTA ct owns h-dims [ct*16, ct*16+16).
// It computes only the 64 gate rows of u = Whh @ h_node that it consumes,
// into an smem ring (parents <= 4 back). One global barrier per step (cz),
// whose release now orders only 64 arc stores + 64 vector REDs.
__global__ void __launch_bounds__(512, 1) recur_kernel(
    const float* __restrict__ Whh_f, const float* __restrict__ Whh_b,
    const float* __restrict__ Wa, const float* __restrict__ Wao,
    const float* __restrict__ bao)
{
    const int dir = blockIdx.x >> 5;
    const int ct  = blockIdx.x & 31;
    const int tid = threadIdx.x;
    const int w = tid >> 5, l = tid & 31;

    const float* Whh = dir ? Whh_b : Whh_f;
    const float* preX = dir ? g_preB : g_preF;
    float* arc  = dir ? g_arcB : g_arcA;
    float* zArr = g_z[dir];
    int* cz = g_cz[dir];

    __shared__ float sWa[16][64];
    __shared__ float sWao[64];
    __shared__ float sbao;
    __shared__ float h_s[4][16];
    __shared__ float carc_s[4][16];
    __shared__ float logit_s[4];
    __shared__ __align__(16) float hn_s[512];
    __shared__ float u_ring[4][64];   // [node&3][g*16+q]
    __shared__ float c_ring[4][16];   // [node&3][q]

    for (int x = tid; x < 16*64; x += 512){
        int q = x >> 6, a = x & 63;
        sWa[q][a] = Wa[(size_t)a*(Hh+3) + ct*16 + q];
    }
    if (tid < 64) sWao[tid] = Wao[tid];
    if (tid == 0) sbao = bao[0];

    // weights: thread -> local row r=tid>>3 (gate g=r>>4, dim q=r&15),
    // column-pairs (m*8+sub), m=0..31 (conflict-free interleave)
    const int r   = tid >> 3;
    const int sub = tid & 7;
    const int rowG = (r >> 4)*Hh + ct*16 + (r & 15);
    float2 wf[32];
    #pragma unroll
    for (int m=0; m<32; m++)
        wf[m] = *(const float2*)(Whh + (size_t)rowG*Hh + (m*8 + sub)*2);
    __syncthreads();

    // cell mapping (threads 0..63): arc dA, dim qA
    const int dA = tid >> 4, qA = tid & 15;
    const int jj = ct*16 + qA;

    // prefetch pre for t=0
    float pg[4] = {0.f,0.f,0.f,0.f};
    if (tid < 64){
        int i0 = dir ? Nn-1 : 0;
        bool v0 = dir ? (i0+1+dA < Nn) : (i0-1-dA >= 0);
        if (v0){
            size_t e = dir ? ((size_t)(i0+1+dA)*4 + dA) : ((size_t)i0*4 + dA);
            const float* pr = preX + e*G4;
            pg[0]=__ldg(pr+jj); pg[1]=__ldg(pr+Hh+jj);
            pg[2]=__ldg(pr+2*Hh+jj); pg[3]=__ldg(pr+3*Hh+jj);
        }
    }

    for (int t = 0; t < Nn; t++){
        const int i = dir ? (Nn-1-t) : t;

        // ---- Phase A: cell (threads 0..63); u/c from local smem ring ----
        if (tid < 64){
            bool valid = dir ? (i+1+dA < Nn) : (i-1-dA >= 0);
            float ha = 0.f, ca = 0.f;
            if (valid){
                int p  = dir ? (i+1+dA) : (i-1-dA);
                int ps = p & 3;
                float gi = pg[0] + u_ring[ps][qA];
                float gf = pg[1] + u_ring[ps][16 + qA];
                float gg = pg[2] + u_ring[ps][32 + qA];
                float go = pg[3] + u_ring[ps][48 + qA];
                float cp = c_ring[ps][qA];
                ca = fsig(gf)*cp + fsig(gi)*ftanh(gg);
                ha = fsig(go)*ftanh(ca);
            }
            h_s[dA][qA] = ha; carc_s[dA][qA] = ca;
            __stcg(arc + ((size_t)i*4 + dA)*Hh + jj, ha);
        }
        __syncthreads();

        // ---- z partials (threads 0..255): slot tid = d*64+a, v4 REDs ---
        if (tid < 256){
            int d = tid >> 6, a = tid & 63;
            float v = 0.f;
            #pragma unroll
            for (int q=0; q<16; q++) v = fmaf(sWa[q][a], h_s[d][q], v);
            float v1 = __shfl_down_sync(0xffffffffu, v, 1);
            float v2 = __shfl_down_sync(0xffffffffu, v, 2);
            float v3 = __shfl_down_sync(0xffffffffu, v, 3);
            if ((tid & 3) == 0)
                red_v4(&zArr[(size_t)i*(64*ZG) + (size_t)(tid>>2)*ZG], v, v1, v2, v3);
        }
        __syncthreads();

        // ---- RELEASE FIRST (publish this CTA's arrival ASAP) ------------
        if (tid == 0) red_rel(&cz[(size_t)i*CPAD]);

        // ---- prefetch next step's pre (hidden under the barrier) -------
        if (tid < 64){
            pg[0]=pg[1]=pg[2]=pg[3]=0.f;
            if (t+1 < Nn){
                int i2 = dir ? (i-1) : (i+1);
                bool v2 = dir ? (i2+1+dA < Nn) : (i2-1-dA >= 0);
                if (v2){
                    size_t e = dir ? ((size_t)(i2+1+dA)*4 + dA) : ((size_t)i2*4 + dA);
                    const float* pr = preX + e*G4;
                    pg[0]=__ldg(pr+jj); pg[1]=__ldg(pr+Hh+jj);
                    pg[2]=__ldg(pr+2*Hh+jj); pg[3]=__ldg(pr+3*Hh+jj);
                }
            }
        }
        if (tid == 0){
            while (ld_acq(&cz[(size_t)i*CPAD]) < NCTA) {}
        }
        __syncthreads();

        // ---- arc loads FIRST (independent), then logits (dependent) ----
        float av[4];
        #pragma unroll
        for (int d=0; d<4; d++)
            av[d] = __ldcg(arc + ((size_t)i*4 + d)*Hh + tid);
        if (w < 4){
            float z1 = __ldcg(&zArr[zaddr(i, w, l)]);
            float z2 = __ldcg(&zArr[zaddr(i, w, l + 32)]);
            float s = fmaxf(z1, 0.f)*sWao[l] + fmaxf(z2, 0.f)*sWao[l + 32];
            #pragma unroll
            for (int off=16; off; off >>= 1) s += __shfl_xor_sync(0xffffffffu, s, off);
            if (l == 0) logit_s[w] = ftanh(s + sbao);
        }
        __syncthreads();

        // ---- softmax weights (redundant per thread) ---------------------
        float wgt[4];
        {
            bool vld[4]; float m = -1e30f; int nv = 0;
            #pragma unroll
            for (int d=0; d<4; d++){
                vld[d] = dir ? (i+1+d < Nn) : (i-1-d >= 0);
                if (vld[d]){ m = fmaxf(m, logit_s[d]); nv++; }
            }
            float ssum = 0.f;
            #pragma unroll
            for (int d=0; d<4; d++){
                float ev = vld[d] ? __expf(logit_s[d]-m) : 0.f;
                wgt[d] = ev; ssum += ev;
            }
            if (nv){
                float inv = 1.f/ssum;
                #pragma unroll
                for (int d=0; d<4; d++) wgt[d] *= inv;
            }
        }

        // ---- h_node into smem; c_node into local ring -------------------
        {
            float h0 = 0.f;
            #pragma unroll
            for (int d=0; d<4; d++) h0 = fmaf(wgt[d], av[d], h0);
            hn_s[tid] = h0;
        }
        if (tid < 16){
            float c = 0.f;
            #pragma unroll
            for (int d=0; d<4; d++) c = fmaf(wgt[d], carc_s[d][tid], c);
            c_ring[i & 3][tid] = c;
        }
        __syncthreads();

        // ---- u rows = Whh_rows @ h_node, f32x2, conflict-free smem ------
        {
            unsigned long long acc0 = 0ull, acc1 = 0ull;
            const unsigned long long* hv = (const unsigned long long*)hn_s;
            #pragma unroll
            for (int m=0; m<32; m+=2){
                ffma2(acc0, *(const unsigned long long*)&wf[m],   hv[m*8 + sub]);
                ffma2(acc1, *(const unsigned long long*)&wf[m+1], hv[(m+1)*8 + sub]);
            }
            float s = __uint_as_float((unsigned)acc0)
                    + __uint_as_float((unsigned)(acc0 >> 32))
                    + __uint_as_float((unsigned)acc1)
                    + __uint_as_float((unsigned)(acc1 >> 32));
            s += __shfl_xor_sync(0xffffffffu, s, 1);
            s += __shfl_xor_sync(0xffffffffu, s, 2);
            s += __shfl_xor_sync(0xffffffffu, s, 4);
            if (sub == 0) u_ring[i & 3][r] = s;
        }
        __syncthreads();   // ring visible before next step's cell
    }
}

// ---------------- final: out[e] = hid[e] . Wdo + bdo --------------------
__global__ void final_kernel(const float* __restrict__ Wdo,
                             const float* __restrict__ bdo,
                             float* __restrict__ out)
{
    int gw = (blockIdx.x*blockDim.x + threadIdx.x) >> 5;
    int l = threadIdx.x & 31;
    if (gw >= Ee) return;
    const float* h = g_hid + (size_t)gw*Hh;
    float s = 0.f;
    #pragma unroll
    for (int q=0; q<16; q++) s = fmaf(h[l + q*32], Wdo[l + q*32], s);
    #pragma unroll
    for (int off=16; off; off >>= 1) s += __shfl_xor_sync(0xffffffffu, s, off);
    if (l == 0) out[gw] = s + bdo[0];
}

// ---------------- launch --------------------------------------------------
extern "C" void kernel_launch(void* const* d_in, const int* in_sizes, int n_in,
                              void* d_out, int out_size)
{
    const float* edges = (const float*)d_in[0];
    const float* Wih_f = (const float*)d_in[1];
    const float* Whh_f = (const float*)d_in[2];
    const float* b_f   = (const float*)d_in[3];
    const float* Wih_b = (const float*)d_in[4];
    const float* Whh_b = (const float*)d_in[5];
    const float* b_b   = (const float*)d_in[6];
    const float* Wa    = (const float*)d_in[7];
    const float* ba    = (const float*)d_in[8];
    const float* Wao   = (const float*)d_in[9];
    const float* bao   = (const float*)d_in[10];
    const float* Wd    = (const float*)d_in[11];
    const float* bd    = (const float*)d_in[12];
    const float* Wdo   = (const float*)d_in[13];
    const float* bdo   = (const float*)d_in[14];
    float* out = (float*)d_out;

    float *preF, *preB, *hid;
    cudaGetSymbolAddress((void**)&preF, g_preF);
    cudaGetSymbolAddress((void**)&preB, g_preB);
    cudaGetSymbolAddress((void**)&hid,  g_hid);

    // 1. counters + z seed
    init_kernel<<<16384, 256>>>(edges, Wa, ba);
    // 2. input-side GEMMs: pre = edges @ Wih^T + b
    gemm_kernel<<<dim3(G4/128, Ee/128), 256>>>(edges, Wih_f, b_f, preF, Ee, G4, Ff, 0);
    gemm_kernel<<<dim3(G4/128, Ee/128), 256>>>(edges, Wih_b, b_b, preB, Ee, G4, Ff, 0);
    // 3. bidirectional recurrence (persistent, 64 CTAs, one sync per step)
    recur_kernel<<<2*NCTA, 512>>>(Whh_f, Whh_b, Wa, Wao, bao);
    // 4. decoder GEMM: hid = relu(feat @ Wd^T + bd), feat gathered from arcs
    gemm_kernel<<<dim3(Hh/128, Ee/128), 256>>>(nullptr, Wd, bd, hid, Ee, Hh, 2*Hh, 1);
    // 5. output projection
    final_kernel<<<(Ee*32)/256, 256>>>(Wdo, bdo, out);
}